// round 6
// baseline (speedup 1.0000x reference)
#include <cuda_runtime.h>

// AdapLoss fused single-kernel, R5: compile-time trip count + 3x batched LDG.128
// + streaming loads (__ldcs) to maximize MLP on the HBM stream.

#define DELTA 5.0f

constexpr int BS = 8;
constexpr long long NPER = 4096000LL;      // 160^3 elements per sample
constexpr int V4 = 1024000;                // NPER / 4 float4's per sample
constexpr int BLOCKS_X = 74;               // 8 * 74 = 592 blocks -> one wave at 4 CTA/SM
constexpr int THREADS = 512;
constexpr int TOTAL_BLOCKS = BS * BLOCKS_X;
constexpr int STRIDE = BLOCKS_X * THREADS;       // 37888
constexpr int FULL_ITERS = V4 / STRIDE;          // 27 (exact batches of 3 below)
constexpr int REM = V4 - FULL_ITERS * STRIDE;    // 1024

// Stage-1 partial sums: [sample][block][{sum_e2, sum_abs, sum_huber}]
__device__ float g_partials[BS][BLOCKS_X][3];
__device__ unsigned int g_counter;   // zero-init; last block resets to 0 for graph replay

__device__ __forceinline__ void accum(float4 a, float4 b,
                                      float& s2, float& s1, float& sh) {
    float e0 = a.x - b.x, e1 = a.y - b.y, e2 = a.z - b.z, e3 = a.w - b.w;
    float a0 = fabsf(e0), a1 = fabsf(e1), a2 = fabsf(e2), a3 = fabsf(e3);
    s2 += e0 * e0 + e1 * e1 + e2 * e2 + e3 * e3;
    s1 += a0 + a1 + a2 + a3;
    // huber: m = min(a, DELTA); h = 0.5*m*m + DELTA*(a - m)   (branch-free)
    float m0 = fminf(a0, DELTA), m1 = fminf(a1, DELTA);
    float m2 = fminf(a2, DELTA), m3 = fminf(a3, DELTA);
    sh += 0.5f * (m0 * m0 + m1 * m1 + m2 * m2 + m3 * m3)
        + DELTA * ((a0 - m0) + (a1 - m1) + (a2 - m2) + (a3 - m3));
}

__global__ __launch_bounds__(THREADS, 3)
void adaploss_fused(const float* __restrict__ pred, const float* __restrict__ tru,
                    float* __restrict__ out) {
    const int s = blockIdx.y;
    const float4* __restrict__ p4 = reinterpret_cast<const float4*>(pred + (long long)s * NPER);
    const float4* __restrict__ t4 = reinterpret_cast<const float4*>(tru  + (long long)s * NPER);

    float s2 = 0.0f, s1 = 0.0f, sh = 0.0f;
    const int base = blockIdx.x * THREADS + threadIdx.x;

    // 27 full iterations in batches of 3: front-batch 6 LDG.128 per batch.
    #pragma unroll 1
    for (int k = 0; k < FULL_ITERS; k += 3) {
        int i0 = base + k * STRIDE;
        int i1 = i0 + STRIDE;
        int i2 = i1 + STRIDE;
        float4 a0 = __ldcs(p4 + i0);
        float4 a1 = __ldcs(p4 + i1);
        float4 a2 = __ldcs(p4 + i2);
        float4 b0 = __ldcs(t4 + i0);
        float4 b1 = __ldcs(t4 + i1);
        float4 b2 = __ldcs(t4 + i2);
        accum(a0, b0, s2, s1, sh);
        accum(a1, b1, s2, s1, sh);
        accum(a2, b2, s2, s1, sh);
    }
    // remainder: first REM global threads take one extra element
    if (base < REM) {
        int i = FULL_ITERS * STRIDE + base;
        float4 a = __ldcs(p4 + i);
        float4 b = __ldcs(t4 + i);
        accum(a, b, s2, s1, sh);
    }

    // intra-warp reduce
    #pragma unroll
    for (int off = 16; off > 0; off >>= 1) {
        s2 += __shfl_down_sync(0xFFFFFFFFu, s2, off);
        s1 += __shfl_down_sync(0xFFFFFFFFu, s1, off);
        sh += __shfl_down_sync(0xFFFFFFFFu, sh, off);
    }

    __shared__ float sm2[THREADS / 32], sm1[THREADS / 32], smh[THREADS / 32];
    __shared__ bool is_last;
    const int lane = threadIdx.x & 31;
    const int wid  = threadIdx.x >> 5;
    if (lane == 0) { sm2[wid] = s2; sm1[wid] = s1; smh[wid] = sh; }
    __syncthreads();

    if (wid == 0) {
        const int NW = THREADS / 32;
        float v2 = (lane < NW) ? sm2[lane] : 0.0f;
        float v1 = (lane < NW) ? sm1[lane] : 0.0f;
        float vh = (lane < NW) ? smh[lane] : 0.0f;
        #pragma unroll
        for (int off = 8; off > 0; off >>= 1) {
            v2 += __shfl_down_sync(0xFFFFFFFFu, v2, off);
            v1 += __shfl_down_sync(0xFFFFFFFFu, v1, off);
            vh += __shfl_down_sync(0xFFFFFFFFu, vh, off);
        }
        if (lane == 0) {
            g_partials[s][blockIdx.x][0] = v2;
            g_partials[s][blockIdx.x][1] = v1;
            g_partials[s][blockIdx.x][2] = vh;
            __threadfence();
            unsigned int prev = atomicAdd(&g_counter, 1u);
            is_last = (prev == (unsigned int)(TOTAL_BLOCKS - 1));
        }
    }
    __syncthreads();
    if (!is_last) return;

    // ---- last block: final reduction over all partials ----
    const int t  = threadIdx.x;
    const int ss = t >> 6;       // 0..7
    const int j  = t & 63;       // 0..63

    double d2 = (j < BLOCKS_X) ? (double)g_partials[ss][j][0] : 0.0;
    double d1 = (j < BLOCKS_X) ? (double)g_partials[ss][j][1] : 0.0;
    double dh = (j < BLOCKS_X) ? (double)g_partials[ss][j][2] : 0.0;
    if (j + 64 < BLOCKS_X) {
        d2 += (double)g_partials[ss][j + 64][0];
        d1 += (double)g_partials[ss][j + 64][1];
        dh += (double)g_partials[ss][j + 64][2];
    }

    #pragma unroll
    for (int off = 16; off > 0; off >>= 1) {
        d2 += __shfl_down_sync(0xFFFFFFFFu, d2, off);
        d1 += __shfl_down_sync(0xFFFFFFFFu, d1, off);
        dh += __shfl_down_sync(0xFFFFFFFFu, dh, off);
    }

    __shared__ double w2[16], w1[16], wh[16];
    __shared__ double per_sample[BS];
    if ((t & 31) == 0) { w2[t >> 5] = d2; w1[t >> 5] = d1; wh[t >> 5] = dh; }
    __syncthreads();

    if (t < BS) {
        double inv = 1.0 / (double)NPER;
        double L2 = (w2[2 * t] + w2[2 * t + 1]) * inv;
        double L1 = (w1[2 * t] + w1[2 * t + 1]) * inv;
        double HU = (wh[2 * t] + wh[2 * t + 1]) * inv;
        bool use_l2 = (L2 <= 1.0) || (L2 < L1 * L1);
        per_sample[t] = use_l2 ? L2 : HU;
    }
    __syncthreads();

    if (t == 0) {
        double acc = 0.0;
        #pragma unroll
        for (int k = 0; k < BS; k++) acc += per_sample[k];
        out[0] = (float)(acc / (double)BS);
        g_counter = 0u;   // reset for next graph replay
    }
}

extern "C" void kernel_launch(void* const* d_in, const int* in_sizes, int n_in,
                              void* d_out, int out_size) {
    const float* pred = (const float*)d_in[0];
    const float* tru  = (const float*)d_in[1];
    float* out = (float*)d_out;

    dim3 grid(BLOCKS_X, BS);
    adaploss_fused<<<grid, THREADS>>>(pred, tru, out);
}

// round 7
// speedup vs baseline: 1.0281x; 1.0281x over previous
#include <cuda_runtime.h>

// AdapLoss fused single-kernel, R6: per-sample dynamic work-stealing (chunked,
// double-buffered) to eliminate CTA straggler spread; last-block-done finish.

#define DELTA 5.0f

constexpr int BS = 8;
constexpr long long NPER = 4096000LL;      // 160^3 elements per sample
constexpr int V4 = 1024000;                // float4's per sample
constexpr int BLOCKS_X = 74;               // 592 blocks -> one wave at 4 CTA/SM
constexpr int THREADS = 512;
constexpr int TOTAL_BLOCKS = BS * BLOCKS_X;
constexpr int NCH = V4 / THREADS;          // 2000 chunks per sample (exact)

// Stage-1 partial sums + dynamic-scheduling state
__device__ float g_partials[BS][BLOCKS_X][3];
__device__ unsigned int g_next[BS];        // per-sample chunk tickets (zero-init)
__device__ unsigned int g_counter;         // finish counter (zero-init)

__device__ __forceinline__ void accum(float4 a, float4 b,
                                      float& s2, float& s1, float& sh) {
    float e0 = a.x - b.x, e1 = a.y - b.y, e2 = a.z - b.z, e3 = a.w - b.w;
    float a0 = fabsf(e0), a1 = fabsf(e1), a2 = fabsf(e2), a3 = fabsf(e3);
    s2 += e0 * e0 + e1 * e1 + e2 * e2 + e3 * e3;
    s1 += a0 + a1 + a2 + a3;
    float h0 = (a0 <= DELTA) ? 0.5f * e0 * e0 : DELTA * (a0 - 0.5f * DELTA);
    float h1 = (a1 <= DELTA) ? 0.5f * e1 * e1 : DELTA * (a1 - 0.5f * DELTA);
    float h2 = (a2 <= DELTA) ? 0.5f * e2 * e2 : DELTA * (a2 - 0.5f * DELTA);
    float h3 = (a3 <= DELTA) ? 0.5f * e3 * e3 : DELTA * (a3 - 0.5f * DELTA);
    sh += h0 + h1 + h2 + h3;
}

__global__ __launch_bounds__(THREADS)
void adaploss_fused(const float* __restrict__ pred, const float* __restrict__ tru,
                    float* __restrict__ out) {
    const int s = blockIdx.y;
    const float4* __restrict__ p4 = reinterpret_cast<const float4*>(pred + (long long)s * NPER);
    const float4* __restrict__ t4 = reinterpret_cast<const float4*>(tru  + (long long)s * NPER);

    __shared__ int s_chunk[2];
    __shared__ bool is_last;
    const int tid = threadIdx.x;

    float s2 = 0.0f, s1 = 0.0f, sh = 0.0f;

    // Dynamic chunk loop, double-buffered: loads for chunk k+1 are issued before
    // the accumulate of chunk k, so memory stays busy across the per-chunk barrier.
    if (tid == 0) s_chunk[0] = (int)atomicAdd(&g_next[s], 1u);
    __syncthreads();
    int cur = s_chunk[0];
    int par = 0;

    float4 a_cur, b_cur;
    if (cur < NCH) {
        a_cur = __ldcs(p4 + cur * THREADS + tid);
        b_cur = __ldcs(t4 + cur * THREADS + tid);
    }

    while (cur < NCH) {
        if (tid == 0) s_chunk[par ^ 1] = (int)atomicAdd(&g_next[s], 1u);
        __syncthreads();
        const int nxt = s_chunk[par ^ 1];
        par ^= 1;

        float4 a_n, b_n;
        if (nxt < NCH) {
            a_n = __ldcs(p4 + nxt * THREADS + tid);
            b_n = __ldcs(t4 + nxt * THREADS + tid);
        }

        accum(a_cur, b_cur, s2, s1, sh);   // data arrived during previous chunk
        a_cur = a_n; b_cur = b_n;
        cur = nxt;
    }

    // intra-warp reduce
    #pragma unroll
    for (int off = 16; off > 0; off >>= 1) {
        s2 += __shfl_down_sync(0xFFFFFFFFu, s2, off);
        s1 += __shfl_down_sync(0xFFFFFFFFu, s1, off);
        sh += __shfl_down_sync(0xFFFFFFFFu, sh, off);
    }

    __shared__ float sm2[THREADS / 32], sm1[THREADS / 32], smh[THREADS / 32];
    const int lane = tid & 31;
    const int wid  = tid >> 5;
    if (lane == 0) { sm2[wid] = s2; sm1[wid] = s1; smh[wid] = sh; }
    __syncthreads();

    if (wid == 0) {
        const int NW = THREADS / 32;
        float v2 = (lane < NW) ? sm2[lane] : 0.0f;
        float v1 = (lane < NW) ? sm1[lane] : 0.0f;
        float vh = (lane < NW) ? smh[lane] : 0.0f;
        #pragma unroll
        for (int off = 8; off > 0; off >>= 1) {
            v2 += __shfl_down_sync(0xFFFFFFFFu, v2, off);
            v1 += __shfl_down_sync(0xFFFFFFFFu, v1, off);
            vh += __shfl_down_sync(0xFFFFFFFFu, vh, off);
        }
        if (lane == 0) {
            g_partials[s][blockIdx.x][0] = v2;
            g_partials[s][blockIdx.x][1] = v1;
            g_partials[s][blockIdx.x][2] = vh;
            __threadfence();
            unsigned int prev = atomicAdd(&g_counter, 1u);
            is_last = (prev == (unsigned int)(TOTAL_BLOCKS - 1));
        }
    }
    __syncthreads();
    if (!is_last) return;

    // ---- last block: final reduction over all partials ----
    const int t  = tid;
    const int ss = t >> 6;       // 0..7
    const int j  = t & 63;       // 0..63

    double d2 = (j < BLOCKS_X) ? (double)g_partials[ss][j][0] : 0.0;
    double d1 = (j < BLOCKS_X) ? (double)g_partials[ss][j][1] : 0.0;
    double dh = (j < BLOCKS_X) ? (double)g_partials[ss][j][2] : 0.0;
    if (j + 64 < BLOCKS_X) {
        d2 += (double)g_partials[ss][j + 64][0];
        d1 += (double)g_partials[ss][j + 64][1];
        dh += (double)g_partials[ss][j + 64][2];
    }

    #pragma unroll
    for (int off = 16; off > 0; off >>= 1) {
        d2 += __shfl_down_sync(0xFFFFFFFFu, d2, off);
        d1 += __shfl_down_sync(0xFFFFFFFFu, d1, off);
        dh += __shfl_down_sync(0xFFFFFFFFu, dh, off);
    }

    __shared__ double w2[16], w1[16], wh[16];
    __shared__ double per_sample[BS];
    if ((t & 31) == 0) { w2[t >> 5] = d2; w1[t >> 5] = d1; wh[t >> 5] = dh; }
    __syncthreads();

    if (t < BS) {
        double inv = 1.0 / (double)NPER;
        double L2 = (w2[2 * t] + w2[2 * t + 1]) * inv;
        double L1 = (w1[2 * t] + w1[2 * t + 1]) * inv;
        double HU = (wh[2 * t] + wh[2 * t + 1]) * inv;
        bool use_l2 = (L2 <= 1.0) || (L2 < L1 * L1);
        per_sample[t] = use_l2 ? L2 : HU;
    }
    __syncthreads();

    if (t == 0) {
        double acc = 0.0;
        #pragma unroll
        for (int k = 0; k < BS; k++) acc += per_sample[k];
        out[0] = (float)(acc / (double)BS);
        // reset scheduling state for next graph replay (all blocks are done here)
        #pragma unroll
        for (int k = 0; k < BS; k++) g_next[k] = 0u;
        g_counter = 0u;
    }
}

extern "C" void kernel_launch(void* const* d_in, const int* in_sizes, int n_in,
                              void* d_out, int out_size) {
    const float* pred = (const float*)d_in[0];
    const float* tru  = (const float*)d_in[1];
    float* out = (float*)d_out;

    dim3 grid(BLOCKS_X, BS);
    adaploss_fused<<<grid, THREADS>>>(pred, tru, out);
}

// round 9
// speedup vs baseline: 1.0462x; 1.0177x over previous
#include <cuda_runtime.h>

// AdapLoss fused single-kernel, R8: static streaming loop + per-sample
// distributed finish (sample finishers overlap with other samples' streaming).

#define DELTA 5.0f

constexpr int BS = 8;
constexpr long long NPER = 4096000LL;      // 160^3 elements per sample
constexpr int V4 = 1024000;                // float4's per sample
constexpr int BLOCKS_X = 74;               // 592 blocks -> one wave at 4 CTA/SM
constexpr int THREADS = 512;
constexpr int NCH = V4 / THREADS;          // 2000 chunks per sample (exact)

// Reduction state (all zero-init at module load; reset in-kernel for replay)
__device__ float  g_partials[BS][BLOCKS_X][3];
__device__ double g_sample[BS];
__device__ unsigned int g_scount[BS];      // per-sample arrival counters
__device__ unsigned int g_done;            // sample-finisher counter

__device__ __forceinline__ void accum(float4 a, float4 b,
                                      float& s2, float& s1, float& sh) {
    float e0 = a.x - b.x, e1 = a.y - b.y, e2 = a.z - b.z, e3 = a.w - b.w;
    float a0 = fabsf(e0), a1 = fabsf(e1), a2 = fabsf(e2), a3 = fabsf(e3);
    s2 += e0 * e0 + e1 * e1 + e2 * e2 + e3 * e3;
    s1 += a0 + a1 + a2 + a3;
    float h0 = (a0 <= DELTA) ? 0.5f * e0 * e0 : DELTA * (a0 - 0.5f * DELTA);
    float h1 = (a1 <= DELTA) ? 0.5f * e1 * e1 : DELTA * (a1 - 0.5f * DELTA);
    float h2 = (a2 <= DELTA) ? 0.5f * e2 * e2 : DELTA * (a2 - 0.5f * DELTA);
    float h3 = (a3 <= DELTA) ? 0.5f * e3 * e3 : DELTA * (a3 - 0.5f * DELTA);
    sh += h0 + h1 + h2 + h3;
}

__global__ __launch_bounds__(THREADS)
void adaploss_fused(const float* __restrict__ pred, const float* __restrict__ tru,
                    float* __restrict__ out) {
    const int s   = blockIdx.y;
    const int tid = threadIdx.x;
    const float4* __restrict__ p4 = reinterpret_cast<const float4*>(pred + (long long)s * NPER);
    const float4* __restrict__ t4 = reinterpret_cast<const float4*>(tru  + (long long)s * NPER);

    float s2 = 0.0f, s1 = 0.0f, sh = 0.0f;

    // Static chunked grid-stride: block b takes chunks b, b+74, ... (27 or 28 iters)
    #pragma unroll 1
    for (int c = blockIdx.x; c < NCH; c += BLOCKS_X) {
        const int i = c * THREADS + tid;
        float4 a = __ldcs(p4 + i);
        float4 b = __ldcs(t4 + i);
        accum(a, b, s2, s1, sh);
    }

    // intra-warp reduce
    #pragma unroll
    for (int off = 16; off > 0; off >>= 1) {
        s2 += __shfl_down_sync(0xFFFFFFFFu, s2, off);
        s1 += __shfl_down_sync(0xFFFFFFFFu, s1, off);
        sh += __shfl_down_sync(0xFFFFFFFFu, sh, off);
    }

    __shared__ float sm2[THREADS / 32], sm1[THREADS / 32], smh[THREADS / 32];
    __shared__ bool sample_finisher;
    const int lane = tid & 31;
    const int wid  = tid >> 5;
    if (lane == 0) { sm2[wid] = s2; sm1[wid] = s1; smh[wid] = sh; }
    __syncthreads();

    if (wid == 0) {
        const int NW = THREADS / 32;
        float v2 = (lane < NW) ? sm2[lane] : 0.0f;
        float v1 = (lane < NW) ? sm1[lane] : 0.0f;
        float vh = (lane < NW) ? smh[lane] : 0.0f;
        #pragma unroll
        for (int off = 8; off > 0; off >>= 1) {
            v2 += __shfl_down_sync(0xFFFFFFFFu, v2, off);
            v1 += __shfl_down_sync(0xFFFFFFFFu, v1, off);
            vh += __shfl_down_sync(0xFFFFFFFFu, vh, off);
        }
        if (lane == 0) {
            g_partials[s][blockIdx.x][0] = v2;
            g_partials[s][blockIdx.x][1] = v1;
            g_partials[s][blockIdx.x][2] = vh;
            __threadfence();
            unsigned int prev = atomicAdd(&g_scount[s], 1u);
            sample_finisher = (prev == (unsigned int)(BLOCKS_X - 1));
        }
    }
    __syncthreads();
    if (!sample_finisher) return;

    // ---- per-sample finisher: reduce this sample's 74 partials ----
    // Warp 0 does it alone: 74 triples, 3 lanes-stride passes, double accumulation.
    if (wid == 0) {
        double d2 = 0.0, d1 = 0.0, dh = 0.0;
        for (int j = lane; j < BLOCKS_X; j += 32) {
            d2 += (double)g_partials[s][j][0];
            d1 += (double)g_partials[s][j][1];
            dh += (double)g_partials[s][j][2];
        }
        #pragma unroll
        for (int off = 16; off > 0; off >>= 1) {
            d2 += __shfl_down_sync(0xFFFFFFFFu, d2, off);
            d1 += __shfl_down_sync(0xFFFFFFFFu, d1, off);
            dh += __shfl_down_sync(0xFFFFFFFFu, dh, off);
        }
        if (lane == 0) {
            const double inv = 1.0 / (double)NPER;
            double L2 = d2 * inv;
            double L1 = d1 * inv;
            double HU = dh * inv;
            bool use_l2 = (L2 <= 1.0) || (L2 < L1 * L1);
            g_sample[s] = use_l2 ? L2 : HU;
            g_scount[s] = 0u;                 // reset for next graph replay
            __threadfence();
            unsigned int prev = atomicAdd(&g_done, 1u);
            if (prev == (unsigned int)(BS - 1)) {
                // ---- global finisher: fixed-order 8-way combine ----
                double acc = 0.0;
                #pragma unroll
                for (int k = 0; k < BS; k++) acc += g_sample[k];
                out[0] = (float)(acc / (double)BS);
                g_done = 0u;                  // reset for next graph replay
            }
        }
    }
}

extern "C" void kernel_launch(void* const* d_in, const int* in_sizes, int n_in,
                              void* d_out, int out_size) {
    const float* pred = (const float*)d_in[0];
    const float* tru  = (const float*)d_in[1];
    float* out = (float*)d_out;

    dim3 grid(BLOCKS_X, BS);
    adaploss_fused<<<grid, THREADS>>>(pred, tru, out);
}